// round 7
// baseline (speedup 1.0000x reference)
#include <cuda_runtime.h>
#include <math.h>

#define DOF 7
#define BATCH 16384
#define NTHREADS 96          // 3 warps per block, 32 elements/block
#define ACTION_RANGE 50.0f
#define MAX_VEL 20.0f
#define TSTEP 0.1f

struct Params {
    float w[DOF][3];
    float v[DOF][3];
    float wxv[DOF][3];
    float wdv[DOF];
    float Rm[DOF][9];     // trans_inv(Mlist[i]) rotation
    float pm[DOF][3];     // trans_inv(Mlist[i]) translation
    float Gd[DOF][6];
    float Mr[DOF + 1][9]; // Mlist rotations (FK)
    float Mp[DOF + 1][3]; // Mlist translations (FK)
    float M66;            // constant diagonal entry S6^T G6 S6
};

__device__ __forceinline__ void cross3(const float* a, const float* b, float* o) {
    o[0] = a[1] * b[2] - a[2] * b[1];
    o[1] = a[2] * b[0] - a[0] * b[2];
    o[2] = a[0] * b[1] - a[1] * b[0];
}

__device__ __forceinline__ void load_adj(const float4 (*abuf)[32], int lane, int i,
                                         float* R, float* p) {
    float4 c0 = abuf[3 * i + 0][lane];
    float4 c1 = abuf[3 * i + 1][lane];
    float4 c2 = abuf[3 * i + 2][lane];
    R[0] = c0.x; R[1] = c0.y; R[2] = c0.z; R[3] = c0.w;
    R[4] = c1.x; R[5] = c1.y; R[6] = c1.z; R[7] = c1.w;
    R[8] = c2.x; p[0] = c2.y; p[1] = c2.z; p[2] = c2.w;
}

// AdT @ V : out_w = R w_in ; out_v = p x out_w + R v_in
__device__ __forceinline__ void adV_rp(const float* R, const float* p,
                                       const float* in, float* out) {
    float a0 = R[0] * in[0] + R[1] * in[1] + R[2] * in[2];
    float a1 = R[3] * in[0] + R[4] * in[1] + R[5] * in[2];
    float a2 = R[6] * in[0] + R[7] * in[1] + R[8] * in[2];
    float b0 = R[0] * in[3] + R[1] * in[4] + R[2] * in[5];
    float b1 = R[3] * in[3] + R[4] * in[4] + R[5] * in[5];
    float b2 = R[6] * in[3] + R[7] * in[4] + R[8] * in[5];
    out[0] = a0; out[1] = a1; out[2] = a2;
    out[3] = b0 + p[1] * a2 - p[2] * a1;
    out[4] = b1 + p[2] * a0 - p[0] * a2;
    out[5] = b2 + p[0] * a1 - p[1] * a0;
}

// AdT^T @ F : out_m = R^T (m + f x p) ; out_f = R^T f
__device__ __forceinline__ void adTF_rp(const float* R, const float* p,
                                        const float* in, float* out) {
    float m0 = in[0] + in[4] * p[2] - in[5] * p[1];
    float m1 = in[1] + in[5] * p[0] - in[3] * p[2];
    float m2 = in[2] + in[3] * p[1] - in[4] * p[0];
    out[0] = R[0] * m0 + R[3] * m1 + R[6] * m2;
    out[1] = R[1] * m0 + R[4] * m1 + R[7] * m2;
    out[2] = R[2] * m0 + R[5] * m1 + R[8] * m2;
    out[3] = R[0] * in[3] + R[3] * in[4] + R[6] * in[5];
    out[4] = R[1] * in[3] + R[4] * in[4] + R[7] * in[5];
    out[5] = R[2] * in[3] + R[5] * in[4] + R[8] * in[5];
}

__device__ __forceinline__ float dot6(const float* F, const float* w, const float* v) {
    return F[0] * w[0] + F[1] * w[1] + F[2] * w[2]
         + F[3] * v[0] + F[4] * v[1] + F[5] * v[2];
}

#define MTRI(i, j) Mtri[((i) * ((i) + 1)) / 2 + (j)]   // i >= j
// Exchange layout: [0..6] bias ; col j lower-tri entries start at colbase(j)
__device__ __forceinline__ constexpr int colbase(int j) {
    return (j == 0) ? 7 : (j == 1) ? 14 : (j == 2) ? 20 : (j == 3) ? 25
         : (j == 4) ? 29 : (j == 5) ? 32 : 34;
}

// Build adjoint for joint i from q_i, write (R,p) to shared.
__device__ __forceinline__ void build_adj(const Params& sp, float q, int i, int lane,
                                          float4 (*abuf)[32]) {
    float s, c;
    __sincosf(q, &s, &c);
    float th = -q, se = -s;
    const float* w = sp.w[i];
    const float* v = sp.v[i];
    float omc = 1.0f - c;
    float Re[9];
    Re[0] = c + omc * w[0] * w[0];
    Re[1] = se * (-w[2]) + omc * w[0] * w[1];
    Re[2] = se * ( w[1]) + omc * w[0] * w[2];
    Re[3] = se * ( w[2]) + omc * w[1] * w[0];
    Re[4] = c + omc * w[1] * w[1];
    Re[5] = se * (-w[0]) + omc * w[1] * w[2];
    Re[6] = se * (-w[1]) + omc * w[2] * w[0];
    Re[7] = se * ( w[0]) + omc * w[2] * w[1];
    Re[8] = c + omc * w[2] * w[2];
    float tms = th - se;
    float pe[3];
#pragma unroll
    for (int k = 0; k < 3; k++)
        pe[k] = th * v[k] + omc * sp.wxv[i][k] + tms * (w[k] * sp.wdv[i] - v[k]);
    const float* Rm = sp.Rm[i];
    float R[9];
#pragma unroll
    for (int r = 0; r < 3; r++)
#pragma unroll
        for (int cc = 0; cc < 3; cc++)
            R[r * 3 + cc] = Re[r * 3 + 0] * Rm[0 * 3 + cc]
                          + Re[r * 3 + 1] * Rm[1 * 3 + cc]
                          + Re[r * 3 + 2] * Rm[2 * 3 + cc];
    float p[3];
#pragma unroll
    for (int r = 0; r < 3; r++)
        p[r] = Re[r * 3 + 0] * sp.pm[i][0] + Re[r * 3 + 1] * sp.pm[i][1]
             + Re[r * 3 + 2] * sp.pm[i][2] + pe[r];
    abuf[3 * i + 0][lane] = make_float4(R[0], R[1], R[2], R[3]);
    abuf[3 * i + 1][lane] = make_float4(R[4], R[5], R[6], R[7]);
    abuf[3 * i + 2][lane] = make_float4(R[8], p[0], p[1], p[2]);
}

// Mass-matrix column J (rows J..6), register scratch, adjoints from shared.
template<int J>
__device__ __forceinline__ void mass_col(const float4 (*abuf)[32], int lane,
                                         const Params& sp, float (*xch)[32]) {
    float vd[DOF][6];
#pragma unroll
    for (int k = 0; k < 3; k++) { vd[J][k] = sp.w[J][k]; vd[J][3 + k] = sp.v[J][k]; }
#pragma unroll
    for (int i = J + 1; i < DOF; i++) {
        float R[9], p[3];
        load_adj(abuf, lane, i, R, p);
        adV_rp(R, p, vd[i - 1], vd[i]);
    }
    float F[6];
#pragma unroll
    for (int k = 0; k < 6; k++) F[k] = sp.Gd[DOF - 1][k] * vd[DOF - 1][k];
    xch[colbase(J) + (DOF - 1) - J][lane] = dot6(F, sp.w[DOF - 1], sp.v[DOF - 1]);
#pragma unroll
    for (int ii = DOF - 2; ii >= J; ii--) {
        float R[9], p[3];
        load_adj(abuf, lane, ii + 1, R, p);
        float X[6];
        adTF_rp(R, p, F, X);
#pragma unroll
        for (int k = 0; k < 6; k++) F[k] = X[k] + sp.Gd[ii][k] * vd[ii][k];
        xch[colbase(J) + ii - J][lane] = dot6(F, sp.w[ii], sp.v[ii]);
    }
}

// Bias inverse dynamics, register scratch, adjoints from shared.
__device__ __forceinline__ void bias_calc(const float4 (*abuf)[32], int lane,
                                          const Params& sp, const float* dqc,
                                          const float* g, float (*xch)[32]) {
    float fb[DOF][6];
    {
        float V[6] = { 0, 0, 0, 0, 0, 0 };
        float Vd[6] = { 0, 0, 0, -g[0], -g[1], -g[2] };
#pragma unroll
        for (int i = 0; i < DOF; i++) {
            float R[9], p[3];
            load_adj(abuf, lane, i, R, p);
            float t[6];
            adV_rp(R, p, V, t);
#pragma unroll
            for (int k = 0; k < 3; k++) {
                V[k]     = t[k]     + sp.w[i][k] * dqc[i];
                V[3 + k] = t[3 + k] + sp.v[i][k] * dqc[i];
            }
            float t2[6];
            adV_rp(R, p, Vd, t2);
            float aw[3], av1[3], av2[3];
            cross3(&V[0], sp.w[i], aw);
            cross3(&V[3], sp.w[i], av1);
            cross3(&V[0], sp.v[i], av2);
#pragma unroll
            for (int k = 0; k < 3; k++) {
                Vd[k]     = t2[k]     + aw[k] * dqc[i];
                Vd[3 + k] = t2[3 + k] + (av1[k] + av2[k]) * dqc[i];
            }
            float GV[6], GVd[6];
#pragma unroll
            for (int k = 0; k < 6; k++) {
                GV[k]  = sp.Gd[i][k] * V[k];
                GVd[k] = sp.Gd[i][k] * Vd[k];
            }
            float c1[3], c2[3], c3[3];
            cross3(&V[0], &GV[0], c1);
            cross3(&V[3], &GV[3], c2);
            cross3(&V[0], &GV[3], c3);
#pragma unroll
            for (int k = 0; k < 3; k++) {
                fb[i][k]     = GVd[k]     + c1[k] + c2[k];
                fb[i][3 + k] = GVd[3 + k] + c3[k];
            }
        }
    }
    float F[6];
#pragma unroll
    for (int k = 0; k < 6; k++) F[k] = fb[DOF - 1][k];
    xch[DOF - 1][lane] = dot6(F, sp.w[DOF - 1], sp.v[DOF - 1]);
#pragma unroll
    for (int ii = DOF - 2; ii >= 0; ii--) {
        float R[9], p[3];
        load_adj(abuf, lane, ii + 1, R, p);
        float X[6];
        adTF_rp(R, p, F, X);
#pragma unroll
        for (int k = 0; k < 6; k++) F[k] = X[k] + fb[ii][k];
        xch[ii][lane] = dot6(F, sp.w[ii], sp.v[ii]);
    }
}

// ---------------------------------------------------------------------------
// Fused kernel: per-block setup + 3-warp role split, RK state in shared.
// ---------------------------------------------------------------------------
__global__ void __launch_bounds__(NTHREADS, 4)
arm_kernel(const float* __restrict__ state, const float* __restrict__ action,
           const float* __restrict__ M_, const float* __restrict__ A_,
           const float* __restrict__ G_, const float* __restrict__ gravity,
           float* __restrict__ out) {
    __shared__ Params sp;
    __shared__ float4 abuf[21][32];   // per-lane adjoints (R,p) x 7 joints
    __shared__ float xch[35][32];     // bias (7) + lower-tri mass (28)
    __shared__ float s_q0[DOF][32], s_dq0[DOF][32], s_tq[DOF][32];
    __shared__ float s_qc[DOF][32], s_dqc[DOF][32];
    __shared__ float s_qs[DOF][32], s_dqs[DOF][32];

    const int tid = threadIdx.x;
    const int lane = tid & 31;
    const int role = tid >> 5;           // 0..2
    const int b = blockIdx.x * 32 + lane;

    // ---- per-block setup (threads 0..14) ----
    if (tid < 8) {
        int m = tid;
        const float* M = M_ + m * 16;
        float a1[3], a2[3], p[3];
#pragma unroll
        for (int r = 0; r < 3; r++) { a1[r] = M[r * 4 + 0]; a2[r] = M[r * 4 + 1]; p[r] = M[r * 4 + 3]; }
        float n1 = sqrtf(a1[0] * a1[0] + a1[1] * a1[1] + a1[2] * a1[2]);
        float b1[3] = { a1[0] / n1, a1[1] / n1, a1[2] / n1 };
        float d = a2[0] * b1[0] + a2[1] * b1[1] + a2[2] * b1[2];
        float a2o[3] = { a2[0] - d * b1[0], a2[1] - d * b1[1], a2[2] - d * b1[2] };
        float n2 = sqrtf(a2o[0] * a2o[0] + a2o[1] * a2o[1] + a2o[2] * a2o[2]);
        float b2[3] = { a2o[0] / n2, a2o[1] / n2, a2o[2] / n2 };
        float b3[3]; cross3(b1, b2, b3);
        float R[9];
#pragma unroll
        for (int r = 0; r < 3; r++) { R[r * 3 + 0] = b1[r]; R[r * 3 + 1] = b2[r]; R[r * 3 + 2] = b3[r]; }
#pragma unroll
        for (int k = 0; k < 9; k++) sp.Mr[m][k] = R[k];
#pragma unroll
        for (int r = 0; r < 3; r++) sp.Mp[m][r] = p[r];
        if (m < DOF) {
            float Rt_[9];
#pragma unroll
            for (int r = 0; r < 3; r++)
#pragma unroll
                for (int c = 0; c < 3; c++) Rt_[r * 3 + c] = R[c * 3 + r];
#pragma unroll
            for (int k = 0; k < 9; k++) sp.Rm[m][k] = Rt_[k];
#pragma unroll
            for (int r = 0; r < 3; r++)
                sp.pm[m][r] = -(Rt_[r * 3 + 0] * p[0] + Rt_[r * 3 + 1] * p[1] + Rt_[r * 3 + 2] * p[2]);
        }
    } else if (tid < 8 + DOF) {
        int j = tid - 8;
        const float* a = A_ + j * 6;
        float nw = sqrtf(a[0] * a[0] + a[1] * a[1] + a[2] * a[2]);
        float w[3] = { a[0] / nw, a[1] / nw, a[2] / nw };
        float v[3] = { a[3], a[4], a[5] };
#pragma unroll
        for (int k = 0; k < 3; k++) { sp.w[j][k] = w[k]; sp.v[j][k] = v[k]; }
        float wxv[3]; cross3(w, v, wxv);
#pragma unroll
        for (int k = 0; k < 3; k++) sp.wxv[j][k] = wxv[k];
        sp.wdv[j] = w[0] * v[0] + w[1] * v[1] + w[2] * v[2];
        float g0 = fabsf(G_[j * 4 + 0]);
        float g1 = fabsf(G_[j * 4 + 1]);
        float g2 = fabsf(G_[j * 4 + 2]);
        float g3 = fabsf(G_[j * 4 + 3]);
        sp.Gd[j][0] = g0; sp.Gd[j][1] = g1; sp.Gd[j][2] = g2;
        sp.Gd[j][3] = g3; sp.Gd[j][4] = g3; sp.Gd[j][5] = g3;
        if (j == DOF - 1) {
            // M[6][6] = S6^T G6 S6 (constant)
            sp.M66 = g0 * w[0] * w[0] + g1 * w[1] * w[1] + g2 * w[2] * w[2]
                   + g3 * (v[0] * v[0] + v[1] * v[1] + v[2] * v[2]);
        }
    }

    // ---- per-element RK state init (role 0 lanes) ----
    if (role == 0) {
#pragma unroll
        for (int i = 0; i < DOF; i++) {
            float q = state[b * 14 + i];
            float dq = state[b * 14 + DOF + i];
            s_q0[i][lane] = q;  s_qc[i][lane] = q;
            s_dq0[i][lane] = dq; s_dqc[i][lane] = dq;
            s_tq[i][lane] = action[b * DOF + i] * ACTION_RANGE;
            s_qs[i][lane] = 0.f; s_dqs[i][lane] = 0.f;
        }
    }
    float g[3];
    g[0] = gravity[0]; g[1] = gravity[1]; g[2] = gravity[2];
    __syncthreads();

    const float h = TSTEP;

#pragma unroll 1
    for (int st = 0; st < 4; st++) {
        // ---- builds: role0:{0} role1:{1,2,3} role2:{4,5,6} ----
        if (role == 0) {
            build_adj(sp, s_qc[0][lane], 0, lane, abuf);
        } else if (role == 1) {
            build_adj(sp, s_qc[1][lane], 1, lane, abuf);
            build_adj(sp, s_qc[2][lane], 2, lane, abuf);
            build_adj(sp, s_qc[3][lane], 3, lane, abuf);
        } else {
            build_adj(sp, s_qc[4][lane], 4, lane, abuf);
            build_adj(sp, s_qc[5][lane], 5, lane, abuf);
            build_adj(sp, s_qc[6][lane], 6, lane, abuf);
        }
        __syncthreads();

        // ---- dynamics: role0 bias; role1 cols 0,1; role2 cols 2,3,4,5 ----
        if (role == 0) {
            float dqc[DOF];
#pragma unroll
            for (int i = 0; i < DOF; i++) dqc[i] = s_dqc[i][lane];
            bias_calc(abuf, lane, sp, dqc, g, xch);
        } else if (role == 1) {
            mass_col<0>(abuf, lane, sp, xch);
            mass_col<1>(abuf, lane, sp, xch);
        } else {
            mass_col<2>(abuf, lane, sp, xch);
            mass_col<3>(abuf, lane, sp, xch);
            mass_col<4>(abuf, lane, sp, xch);
            mass_col<5>(abuf, lane, sp, xch);
        }
        __syncthreads();

        // ---- solve + RK update (role 0 only; state lives in shared) ----
        if (role == 0) {
            float bias[DOF], Mtri[(DOF * (DOF + 1)) / 2];
#pragma unroll
            for (int i = 0; i < DOF; i++) bias[i] = xch[i][lane];
#pragma unroll
            for (int j = 0; j < DOF - 1; j++)
#pragma unroll
                for (int i = j; i < DOF; i++)
                    MTRI(i, j) = xch[colbase(j) + i - j][lane];
            MTRI(6, 6) = sp.M66;

            float x[DOF], invd[DOF];
#pragma unroll
            for (int i = 0; i < DOF; i++) x[i] = s_tq[i][lane] - bias[i];
#pragma unroll
            for (int k = 0; k < DOF; k++) {
                float inv = __fdividef(1.0f, MTRI(k, k));
                invd[k] = inv;
                float fk[DOF];
#pragma unroll
                for (int i = k + 1; i < DOF; i++) fk[i] = MTRI(i, k) * inv;
#pragma unroll
                for (int i = k + 1; i < DOF; i++) {
                    x[i] -= fk[i] * x[k];
#pragma unroll
                    for (int jj = k + 1; jj <= i; jj++)
                        MTRI(i, jj) -= fk[i] * MTRI(jj, k);
                }
#pragma unroll
                for (int i = k + 1; i < DOF; i++) MTRI(i, k) = fk[i];
            }
#pragma unroll
            for (int i = 0; i < DOF; i++) x[i] *= invd[i];
#pragma unroll
            for (int i = DOF - 2; i >= 0; i--) {
                float s = x[i];
#pragma unroll
                for (int jj = i + 1; jj < DOF; jj++) s -= MTRI(jj, i) * x[jj];
                x[i] = s;
            }

            float wk = (st == 1 || st == 2) ? 2.0f : 1.0f;
            float cc = (st == 2) ? 1.0f : 0.5f;
#pragma unroll
            for (int i = 0; i < DOF; i++) {
                float dqci = s_dqc[i][lane];
                s_qs[i][lane]  += wk * dqci;
                s_dqs[i][lane] += wk * x[i];
                s_qc[i][lane]  = s_q0[i][lane]  + cc * h * dqci;
                s_dqc[i][lane] = s_dq0[i][lane] + cc * h * x[i];
            }
        }
        __syncthreads();
    }

    const float PI = 3.14159265358979323846f;
    const float TWO_PI = 6.28318530717958647692f;
    float qn[DOF];
#pragma unroll
    for (int i = 0; i < DOF; i++) {
        float qv = s_q0[i][lane] + (h / 6.0f) * s_qs[i][lane];
        float t = qv;
        if (qv >= PI) t = qv - TWO_PI;
        else if (qv < -PI) t = qv + TWO_PI;
        qn[i] = t;
    }

    if (role == 0) {
#pragma unroll
        for (int i = 0; i < DOF; i++) {
            out[b * 14 + i] = qn[i];
            float dv = s_dq0[i][lane] + (h / 6.0f) * s_dqs[i][lane];
            dv = fminf(fmaxf(dv, -MAX_VEL), MAX_VEL);
            out[b * 14 + DOF + i] = dv;
        }
        return;
    }

    // ---- FK (roles 1,2): row (role-1) of T; ee component = role-1 ----
    const int fkrow = role - 1;
    float TRr[3] = { fkrow == 0 ? 1.f : 0.f, fkrow == 0 ? 0.f : 1.f, 0.f };
    float Tpr = 0.f;
#pragma unroll
    for (int i = 0; i < DOF; i++) {
        float s, c;
        __sincosf(qn[i], &s, &c);
        const float* w = sp.w[i];
        const float* v = sp.v[i];
        float omc = 1.0f - c;
        float Re[9];
        Re[0] = c + omc * w[0] * w[0];
        Re[1] = s * (-w[2]) + omc * w[0] * w[1];
        Re[2] = s * ( w[1]) + omc * w[0] * w[2];
        Re[3] = s * ( w[2]) + omc * w[1] * w[0];
        Re[4] = c + omc * w[1] * w[1];
        Re[5] = s * (-w[0]) + omc * w[1] * w[2];
        Re[6] = s * (-w[1]) + omc * w[2] * w[0];
        Re[7] = s * ( w[0]) + omc * w[2] * w[1];
        Re[8] = c + omc * w[2] * w[2];
        float th = qn[i];
        float tms = th - s;
        float pe[3];
#pragma unroll
        for (int k = 0; k < 3; k++)
            pe[k] = th * v[k] + omc * sp.wxv[i][k] + tms * (w[k] * sp.wdv[i] - v[k]);
        const float* Mr = sp.Mr[i];
        const float* Mp = sp.Mp[i];
        float Tm[3];
#pragma unroll
        for (int cc2 = 0; cc2 < 3; cc2++)
            Tm[cc2] = TRr[0] * Mr[0 * 3 + cc2] + TRr[1] * Mr[1 * 3 + cc2] + TRr[2] * Mr[2 * 3 + cc2];
        Tpr += TRr[0] * Mp[0] + TRr[1] * Mp[1] + TRr[2] * Mp[2]
             + Tm[0] * pe[0] + Tm[1] * pe[1] + Tm[2] * pe[2];
        float nTR[3];
#pragma unroll
        for (int cc2 = 0; cc2 < 3; cc2++)
            nTR[cc2] = Tm[0] * Re[0 * 3 + cc2] + Tm[1] * Re[1 * 3 + cc2] + Tm[2] * Re[2 * 3 + cc2];
        TRr[0] = nTR[0]; TRr[1] = nTR[1]; TRr[2] = nTR[2];
    }
    const float* Mp7 = sp.Mp[DOF];
    float e = TRr[0] * Mp7[0] + TRr[1] * Mp7[1] + TRr[2] * Mp7[2] + Tpr;
    out[BATCH * 14 + b * 2 + fkrow] = e;
}

extern "C" void kernel_launch(void* const* d_in, const int* in_sizes, int n_in,
                              void* d_out, int out_size) {
    const float* state   = (const float*)d_in[0];
    const float* action  = (const float*)d_in[1];
    const float* M_      = (const float*)d_in[2];
    const float* A_      = (const float*)d_in[3];
    const float* G_      = (const float*)d_in[4];
    const float* gravity = (const float*)d_in[5];
    float* out = (float*)d_out;

    arm_kernel<<<BATCH / 32, NTHREADS>>>(state, action, M_, A_, G_, gravity, out);
}

// round 8
// speedup vs baseline: 1.0804x; 1.0804x over previous
#include <cuda_runtime.h>
#include <math.h>

#define DOF 7
#define BATCH 16384
#define NTHREADS 64          // 2 warps per block, 32 elements/block
#define ACTION_RANGE 50.0f
#define MAX_VEL 20.0f
#define TSTEP 0.1f

struct Params {
    float w[DOF][3];
    float v[DOF][3];
    float wxv[DOF][3];
    float wdv[DOF];
    float Rm[DOF][9];     // trans_inv(Mlist[i]) rotation
    float pm[DOF][3];     // trans_inv(Mlist[i]) translation
    float Gd[DOF][6];
    float Mr[DOF + 1][9]; // Mlist rotations (FK)
    float Mp[DOF + 1][3]; // Mlist translations (FK)
};

__device__ __forceinline__ void cross3(const float* a, const float* b, float* o) {
    o[0] = a[1] * b[2] - a[2] * b[1];
    o[1] = a[2] * b[0] - a[0] * b[2];
    o[2] = a[0] * b[1] - a[1] * b[0];
}

__device__ __forceinline__ void load_adj(const float4 (*abuf)[32], int lane, int i,
                                         float* R, float* p) {
    float4 c0 = abuf[3 * i + 0][lane];
    float4 c1 = abuf[3 * i + 1][lane];
    float4 c2 = abuf[3 * i + 2][lane];
    R[0] = c0.x; R[1] = c0.y; R[2] = c0.z; R[3] = c0.w;
    R[4] = c1.x; R[5] = c1.y; R[6] = c1.z; R[7] = c1.w;
    R[8] = c2.x; p[0] = c2.y; p[1] = c2.z; p[2] = c2.w;
}

// AdT @ V : out_w = R w_in ; out_v = p x out_w + R v_in (safe in==out)
__device__ __forceinline__ void adV_rp(const float* R, const float* p,
                                       const float* in, float* out) {
    float a0 = R[0] * in[0] + R[1] * in[1] + R[2] * in[2];
    float a1 = R[3] * in[0] + R[4] * in[1] + R[5] * in[2];
    float a2 = R[6] * in[0] + R[7] * in[1] + R[8] * in[2];
    float b0 = R[0] * in[3] + R[1] * in[4] + R[2] * in[5];
    float b1 = R[3] * in[3] + R[4] * in[4] + R[5] * in[5];
    float b2 = R[6] * in[3] + R[7] * in[4] + R[8] * in[5];
    out[0] = a0; out[1] = a1; out[2] = a2;
    out[3] = b0 + p[1] * a2 - p[2] * a1;
    out[4] = b1 + p[2] * a0 - p[0] * a2;
    out[5] = b2 + p[0] * a1 - p[1] * a0;
}

// Start offset of column j's vectors in vdbuf (levels k=j..6)
__device__ __forceinline__ constexpr int vofs(int j) {
    return (j == 0) ? 0 : (j == 1) ? 7 : (j == 2) ? 13 : (j == 3) ? 18
         : (j == 4) ? 22 : (j == 5) ? 25 : 27;
}

__device__ __forceinline__ void store_vd(float2 (*vdbuf)[32], int lane, int v,
                                         const float* x) {
    vdbuf[v * 3 + 0][lane] = make_float2(x[0], x[1]);
    vdbuf[v * 3 + 1][lane] = make_float2(x[2], x[3]);
    vdbuf[v * 3 + 2][lane] = make_float2(x[4], x[5]);
}

__device__ __forceinline__ void load_vd(const float2 (*vdbuf)[32], int lane, int v,
                                        float* x) {
    float2 a = vdbuf[v * 3 + 0][lane];
    float2 b = vdbuf[v * 3 + 1][lane];
    float2 c = vdbuf[v * 3 + 2][lane];
    x[0] = a.x; x[1] = a.y; x[2] = b.x; x[3] = b.y; x[4] = c.x; x[5] = c.y;
}

__device__ __forceinline__ float dot6c(const float* a, const float* b) {
    return a[0] * b[0] + a[1] * b[1] + a[2] * b[2]
         + a[3] * b[3] + a[4] * b[4] + a[5] * b[5];
}

#define MTRI(i, j) Mtri[((i) * ((i) + 1)) / 2 + (j)]   // i >= j
// xch layout: [0..6] bias ; col j lower-tri entries start at colbase(j)
__device__ __forceinline__ constexpr int colbase(int j) {
    return (j == 0) ? 7 : (j == 1) ? 14 : (j == 2) ? 20 : (j == 3) ? 25
         : (j == 4) ? 29 : (j == 5) ? 32 : 34;
}

// Build adjoint for joint i from q_i, write (R,p) to shared.
__device__ __forceinline__ void build_adj(const Params& sp, float q, int i, int lane,
                                          float4 (*abuf)[32]) {
    float s, c;
    __sincosf(q, &s, &c);
    float th = -q, se = -s;
    const float* w = sp.w[i];
    const float* v = sp.v[i];
    float omc = 1.0f - c;
    float Re[9];
    Re[0] = c + omc * w[0] * w[0];
    Re[1] = se * (-w[2]) + omc * w[0] * w[1];
    Re[2] = se * ( w[1]) + omc * w[0] * w[2];
    Re[3] = se * ( w[2]) + omc * w[1] * w[0];
    Re[4] = c + omc * w[1] * w[1];
    Re[5] = se * (-w[0]) + omc * w[1] * w[2];
    Re[6] = se * (-w[1]) + omc * w[2] * w[0];
    Re[7] = se * ( w[0]) + omc * w[2] * w[1];
    Re[8] = c + omc * w[2] * w[2];
    float tms = th - se;
    float pe[3];
#pragma unroll
    for (int k = 0; k < 3; k++)
        pe[k] = th * v[k] + omc * sp.wxv[i][k] + tms * (w[k] * sp.wdv[i] - v[k]);
    const float* Rm = sp.Rm[i];
    float R[9];
#pragma unroll
    for (int r = 0; r < 3; r++)
#pragma unroll
        for (int cc = 0; cc < 3; cc++)
            R[r * 3 + cc] = Re[r * 3 + 0] * Rm[0 * 3 + cc]
                          + Re[r * 3 + 1] * Rm[1 * 3 + cc]
                          + Re[r * 3 + 2] * Rm[2 * 3 + cc];
    float p[3];
#pragma unroll
    for (int r = 0; r < 3; r++)
        p[r] = Re[r * 3 + 0] * sp.pm[i][0] + Re[r * 3 + 1] * sp.pm[i][1]
             + Re[r * 3 + 2] * sp.pm[i][2] + pe[r];
    abuf[3 * i + 0][lane] = make_float4(R[0], R[1], R[2], R[3]);
    abuf[3 * i + 1][lane] = make_float4(R[4], R[5], R[6], R[7]);
    abuf[3 * i + 2][lane] = make_float4(R[8], p[0], p[1], p[2]);
}

// ---------------------------------------------------------------------------
// Fused kernel: per-block setup + 2-warp split, backward sweeps replaced by
// parallel dot-products over forward-propagated screws.
// ---------------------------------------------------------------------------
__global__ void __launch_bounds__(NTHREADS)
arm_kernel(const float* __restrict__ state, const float* __restrict__ action,
           const float* __restrict__ M_, const float* __restrict__ A_,
           const float* __restrict__ G_, const float* __restrict__ gravity,
           float* __restrict__ out) {
    __shared__ Params sp;
    __shared__ float4 abuf[21][32];    // adjoints (R,p) x 7 joints
    __shared__ float2 vdbuf[84][32];   // 28 propagated screws x 3 float2
    __shared__ float xch[35][32];      // bias (7) + lower-tri mass (28)

    const int tid = threadIdx.x;
    const int lane = tid & 31;
    const int role = tid >> 5;
    const int b = blockIdx.x * 32 + lane;

    // ---- per-block setup (threads 0..14) ----
    if (tid < 8) {
        int m = tid;
        const float* M = M_ + m * 16;
        float a1[3], a2[3], p[3];
#pragma unroll
        for (int r = 0; r < 3; r++) { a1[r] = M[r * 4 + 0]; a2[r] = M[r * 4 + 1]; p[r] = M[r * 4 + 3]; }
        float n1 = sqrtf(a1[0] * a1[0] + a1[1] * a1[1] + a1[2] * a1[2]);
        float b1[3] = { a1[0] / n1, a1[1] / n1, a1[2] / n1 };
        float d = a2[0] * b1[0] + a2[1] * b1[1] + a2[2] * b1[2];
        float a2o[3] = { a2[0] - d * b1[0], a2[1] - d * b1[1], a2[2] - d * b1[2] };
        float n2 = sqrtf(a2o[0] * a2o[0] + a2o[1] * a2o[1] + a2o[2] * a2o[2]);
        float b2[3] = { a2o[0] / n2, a2o[1] / n2, a2o[2] / n2 };
        float b3[3]; cross3(b1, b2, b3);
        float R[9];
#pragma unroll
        for (int r = 0; r < 3; r++) { R[r * 3 + 0] = b1[r]; R[r * 3 + 1] = b2[r]; R[r * 3 + 2] = b3[r]; }
#pragma unroll
        for (int k = 0; k < 9; k++) sp.Mr[m][k] = R[k];
#pragma unroll
        for (int r = 0; r < 3; r++) sp.Mp[m][r] = p[r];
        if (m < DOF) {
            float Rt_[9];
#pragma unroll
            for (int r = 0; r < 3; r++)
#pragma unroll
                for (int c = 0; c < 3; c++) Rt_[r * 3 + c] = R[c * 3 + r];
#pragma unroll
            for (int k = 0; k < 9; k++) sp.Rm[m][k] = Rt_[k];
#pragma unroll
            for (int r = 0; r < 3; r++)
                sp.pm[m][r] = -(Rt_[r * 3 + 0] * p[0] + Rt_[r * 3 + 1] * p[1] + Rt_[r * 3 + 2] * p[2]);
        }
    } else if (tid < 8 + DOF) {
        int j = tid - 8;
        const float* a = A_ + j * 6;
        float nw = sqrtf(a[0] * a[0] + a[1] * a[1] + a[2] * a[2]);
        float w[3] = { a[0] / nw, a[1] / nw, a[2] / nw };
        float v[3] = { a[3], a[4], a[5] };
#pragma unroll
        for (int k = 0; k < 3; k++) { sp.w[j][k] = w[k]; sp.v[j][k] = v[k]; }
        float wxv[3]; cross3(w, v, wxv);
#pragma unroll
        for (int k = 0; k < 3; k++) sp.wxv[j][k] = wxv[k];
        sp.wdv[j] = w[0] * v[0] + w[1] * v[1] + w[2] * v[2];
        float g0 = fabsf(G_[j * 4 + 0]);
        float g1 = fabsf(G_[j * 4 + 1]);
        float g2 = fabsf(G_[j * 4 + 2]);
        float g3 = fabsf(G_[j * 4 + 3]);
        sp.Gd[j][0] = g0; sp.Gd[j][1] = g1; sp.Gd[j][2] = g2;
        sp.Gd[j][3] = g3; sp.Gd[j][4] = g3; sp.Gd[j][5] = g3;
    }

    float q0[DOF], dq0[DOF], tq[DOF], g[3];
#pragma unroll
    for (int i = 0; i < DOF; i++) {
        q0[i]  = state[b * 14 + i];
        dq0[i] = state[b * 14 + DOF + i];
        tq[i]  = action[b * DOF + i] * ACTION_RANGE;
    }
    g[0] = gravity[0]; g[1] = gravity[1]; g[2] = gravity[2];
    __syncthreads();

    const float h = TSTEP;
    float qs[DOF], dqs[DOF], qc[DOF], dqc[DOF];
#pragma unroll
    for (int i = 0; i < DOF; i++) { qc[i] = q0[i]; dqc[i] = dq0[i]; qs[i] = 0.f; dqs[i] = 0.f; }

#pragma unroll 1
    for (int st = 0; st < 4; st++) {
        // ---- phase 0: builds (role0: 0-2 ; role1: 3-6) ----
        if (role == 0) {
            build_adj(sp, qc[0], 0, lane, abuf);
            build_adj(sp, qc[1], 1, lane, abuf);
            build_adj(sp, qc[2], 2, lane, abuf);
        } else {
            build_adj(sp, qc[3], 3, lane, abuf);
            build_adj(sp, qc[4], 4, lane, abuf);
            build_adj(sp, qc[5], 5, lane, abuf);
            build_adj(sp, qc[6], 6, lane, abuf);
        }
        __syncthreads();   // sync1: abuf complete

        float fb[DOF][6];  // role0 only (per-link wrenches)
        if (role == 0) {
            // ---- forward V/Vd sweep producing fb[k] ----
            float V[6] = { 0, 0, 0, 0, 0, 0 };
            float Vd[6] = { 0, 0, 0, -g[0], -g[1], -g[2] };
#pragma unroll
            for (int i = 0; i < DOF; i++) {
                float R[9], p[3];
                load_adj(abuf, lane, i, R, p);
                float t[6];
                adV_rp(R, p, V, t);
#pragma unroll
                for (int k = 0; k < 3; k++) {
                    V[k]     = t[k]     + sp.w[i][k] * dqc[i];
                    V[3 + k] = t[3 + k] + sp.v[i][k] * dqc[i];
                }
                float t2[6];
                adV_rp(R, p, Vd, t2);
                float aw[3], av1[3], av2[3];
                cross3(&V[0], sp.w[i], aw);
                cross3(&V[3], sp.w[i], av1);
                cross3(&V[0], sp.v[i], av2);
#pragma unroll
                for (int k = 0; k < 3; k++) {
                    Vd[k]     = t2[k]     + aw[k] * dqc[i];
                    Vd[3 + k] = t2[3 + k] + (av1[k] + av2[k]) * dqc[i];
                }
                float GV[6], GVd[6];
#pragma unroll
                for (int k = 0; k < 6; k++) {
                    GV[k]  = sp.Gd[i][k] * V[k];
                    GVd[k] = sp.Gd[i][k] * Vd[k];
                }
                float c1[3], c2[3], c3[3];
                cross3(&V[0], &GV[0], c1);
                cross3(&V[3], &GV[3], c2);
                cross3(&V[0], &GV[3], c3);
#pragma unroll
                for (int k = 0; k < 3; k++) {
                    fb[i][k]     = GVd[k]     + c1[k] + c2[k];
                    fb[i][3 + k] = GVd[3 + k] + c3[k];
                }
            }
        } else {
            // ---- all 7 vd chains, written level-by-level to vdbuf ----
#pragma unroll
            for (int j = 0; j < DOF; j++) {
                float cur[6];
#pragma unroll
                for (int k = 0; k < 3; k++) { cur[k] = sp.w[j][k]; cur[3 + k] = sp.v[j][k]; }
                store_vd(vdbuf, lane, vofs(j), cur);
#pragma unroll
                for (int k = j + 1; k < DOF; k++) {
                    float R[9], p[3];
                    load_adj(abuf, lane, k, R, p);
                    adV_rp(R, p, cur, cur);
                    store_vd(vdbuf, lane, vofs(j) + k - j, cur);
                }
            }
        }
        __syncthreads();   // sync2: fb in role0 regs, vdbuf complete

        // ---- phase 2: parallel dot-products ----
        if (role == 0) {
            // bias[i] = sum_{k>=i} fb_k . vd_i[k] ; M cols 0,1
            float Macc[13];
            float bacc[DOF];
#pragma unroll
            for (int i = 0; i < 13; i++) Macc[i] = 0.f;
#pragma unroll
            for (int i = 0; i < DOF; i++) bacc[i] = 0.f;
#pragma unroll
            for (int k = 0; k < DOF; k++) {
                float vk[DOF][6];
#pragma unroll
                for (int j = 0; j <= k; j++)
                    load_vd(vdbuf, lane, vofs(j) + k - j, vk[j]);
                float gv0[6];
#pragma unroll
                for (int c = 0; c < 6; c++) gv0[c] = sp.Gd[k][c] * vk[0][c];
#pragma unroll
                for (int i = 0; i <= k; i++) Macc[i] += dot6c(vk[i], gv0);
                if (k >= 1) {
                    float gv1[6];
#pragma unroll
                    for (int c = 0; c < 6; c++) gv1[c] = sp.Gd[k][c] * vk[1][c];
#pragma unroll
                    for (int i = 1; i <= k; i++) Macc[6 + i] += dot6c(vk[i], gv1);
                }
#pragma unroll
                for (int i = 0; i <= k; i++) bacc[i] += dot6c(fb[k], vk[i]);
            }
#pragma unroll
            for (int i = 0; i < DOF; i++) xch[i][lane] = bacc[i];
#pragma unroll
            for (int i = 0; i < DOF; i++) xch[colbase(0) + i][lane] = Macc[i];
#pragma unroll
            for (int i = 1; i < DOF; i++) xch[colbase(1) + i - 1][lane] = Macc[6 + i];
        } else {
            // M cols 2..6
            float Macc[15];
#pragma unroll
            for (int i = 0; i < 15; i++) Macc[i] = 0.f;
#pragma unroll
            for (int k = 2; k < DOF; k++) {
                float vk[DOF][6];
#pragma unroll
                for (int j = 2; j <= k; j++)
                    load_vd(vdbuf, lane, vofs(j) + k - j, vk[j]);
#pragma unroll
                for (int j = 2; j <= k; j++) {
                    float gv[6];
#pragma unroll
                    for (int c = 0; c < 6; c++) gv[c] = sp.Gd[k][c] * vk[j][c];
                    const int mo = (j == 2) ? 0 : (j == 3) ? 5 : (j == 4) ? 9 : (j == 5) ? 12 : 14;
#pragma unroll
                    for (int i = j; i <= k; i++) Macc[mo + i - j] += dot6c(vk[i], gv);
                }
            }
#pragma unroll
            for (int j = 2; j < DOF; j++) {
                const int mo = (j == 2) ? 0 : (j == 3) ? 5 : (j == 4) ? 9 : (j == 5) ? 12 : 14;
#pragma unroll
                for (int i = j; i < DOF; i++)
                    xch[colbase(j) + i - j][lane] = Macc[mo + i - j];
            }
        }
        __syncthreads();   // sync3: xch complete

        // ---- solve + RK update (duplicated in both roles) ----
        float bias[DOF], Mtri[(DOF * (DOF + 1)) / 2];
#pragma unroll
        for (int i = 0; i < DOF; i++) bias[i] = xch[i][lane];
#pragma unroll
        for (int j = 0; j < DOF; j++)
#pragma unroll
            for (int i = j; i < DOF; i++)
                MTRI(i, j) = xch[colbase(j) + i - j][lane];

        float x[DOF], invd[DOF];
#pragma unroll
        for (int i = 0; i < DOF; i++) x[i] = tq[i] - bias[i];
#pragma unroll
        for (int k = 0; k < DOF; k++) {
            float inv = __fdividef(1.0f, MTRI(k, k));
            invd[k] = inv;
            float fk[DOF];
#pragma unroll
            for (int i = k + 1; i < DOF; i++) fk[i] = MTRI(i, k) * inv;
#pragma unroll
            for (int i = k + 1; i < DOF; i++) {
                x[i] -= fk[i] * x[k];
#pragma unroll
                for (int jj = k + 1; jj <= i; jj++)
                    MTRI(i, jj) -= fk[i] * MTRI(jj, k);
            }
#pragma unroll
            for (int i = k + 1; i < DOF; i++) MTRI(i, k) = fk[i];
        }
#pragma unroll
        for (int i = 0; i < DOF; i++) x[i] *= invd[i];
#pragma unroll
        for (int i = DOF - 2; i >= 0; i--) {
            float s = x[i];
#pragma unroll
            for (int jj = i + 1; jj < DOF; jj++) s -= MTRI(jj, i) * x[jj];
            x[i] = s;
        }

        float wk = (st == 1 || st == 2) ? 2.0f : 1.0f;
        float cc = (st == 2) ? 1.0f : 0.5f;
#pragma unroll
        for (int i = 0; i < DOF; i++) {
            qs[i]  += wk * dqc[i];
            dqs[i] += wk * x[i];
            qc[i]  = q0[i]  + cc * h * dqc[i];
            dqc[i] = dq0[i] + cc * h * x[i];
        }
    }

    const float PI = 3.14159265358979323846f;
    const float TWO_PI = 6.28318530717958647692f;
    float qn[DOF];
#pragma unroll
    for (int i = 0; i < DOF; i++) {
        float qv = q0[i] + (h / 6.0f) * qs[i];
        float t = qv;
        if (qv >= PI) t = qv - TWO_PI;
        else if (qv < -PI) t = qv + TWO_PI;
        qn[i] = t;
        if (role == 0) {
            out[b * 14 + i] = qn[i];
        } else {
            float dv = dq0[i] + (h / 6.0f) * dqs[i];
            dv = fminf(fmaxf(dv, -MAX_VEL), MAX_VEL);
            out[b * 14 + DOF + i] = dv;
        }
    }

    // ---- FK: row `role` of T propagates independently; ee component = role ----
    float TRr[3] = { role == 0 ? 1.f : 0.f, role == 0 ? 0.f : 1.f, 0.f };
    float Tpr = 0.f;
#pragma unroll
    for (int i = 0; i < DOF; i++) {
        float s, c;
        __sincosf(qn[i], &s, &c);
        const float* w = sp.w[i];
        const float* v = sp.v[i];
        float omc = 1.0f - c;
        float Re[9];
        Re[0] = c + omc * w[0] * w[0];
        Re[1] = s * (-w[2]) + omc * w[0] * w[1];
        Re[2] = s * ( w[1]) + omc * w[0] * w[2];
        Re[3] = s * ( w[2]) + omc * w[1] * w[0];
        Re[4] = c + omc * w[1] * w[1];
        Re[5] = s * (-w[0]) + omc * w[1] * w[2];
        Re[6] = s * (-w[1]) + omc * w[2] * w[0];
        Re[7] = s * ( w[0]) + omc * w[2] * w[1];
        Re[8] = c + omc * w[2] * w[2];
        float th = qn[i];
        float tms = th - s;
        float pe[3];
#pragma unroll
        for (int k = 0; k < 3; k++)
            pe[k] = th * v[k] + omc * sp.wxv[i][k] + tms * (w[k] * sp.wdv[i] - v[k]);
        const float* Mr = sp.Mr[i];
        const float* Mp = sp.Mp[i];
        float Tm[3];
#pragma unroll
        for (int cc2 = 0; cc2 < 3; cc2++)
            Tm[cc2] = TRr[0] * Mr[0 * 3 + cc2] + TRr[1] * Mr[1 * 3 + cc2] + TRr[2] * Mr[2 * 3 + cc2];
        Tpr += TRr[0] * Mp[0] + TRr[1] * Mp[1] + TRr[2] * Mp[2]
             + Tm[0] * pe[0] + Tm[1] * pe[1] + Tm[2] * pe[2];
        float nTR[3];
#pragma unroll
        for (int cc2 = 0; cc2 < 3; cc2++)
            nTR[cc2] = Tm[0] * Re[0 * 3 + cc2] + Tm[1] * Re[1 * 3 + cc2] + Tm[2] * Re[2 * 3 + cc2];
        TRr[0] = nTR[0]; TRr[1] = nTR[1]; TRr[2] = nTR[2];
    }
    const float* Mp7 = sp.Mp[DOF];
    float e = TRr[0] * Mp7[0] + TRr[1] * Mp7[1] + TRr[2] * Mp7[2] + Tpr;
    out[BATCH * 14 + b * 2 + role] = e;
}

extern "C" void kernel_launch(void* const* d_in, const int* in_sizes, int n_in,
                              void* d_out, int out_size) {
    const float* state   = (const float*)d_in[0];
    const float* action  = (const float*)d_in[1];
    const float* M_      = (const float*)d_in[2];
    const float* A_      = (const float*)d_in[3];
    const float* G_      = (const float*)d_in[4];
    const float* gravity = (const float*)d_in[5];
    float* out = (float*)d_out;

    arm_kernel<<<BATCH / 32, NTHREADS>>>(state, action, M_, A_, G_, gravity, out);
}